// round 1
// baseline (speedup 1.0000x reference)
#include <cuda_runtime.h>
#include <math.h>

#define NHH 8
#define ED 256
#define SQL 1024
#define BSZ 4
#define QKV (NHH*3*ED)   /* 6144 */
#define NE  (NHH*ED)     /* 2048 */
#define TOK (BSZ*SQL)    /* 4096 */

// Scratch (device globals; allocation-free per harness rules)
__device__ float g_proj[(size_t)TOK*QKV];          // (b, s, 6144)
__device__ float g_scores[(size_t)BSZ*NHH*SQL*SQL];// (bh, q, k)
__device__ float g_attn[(size_t)TOK*NE];           // (b,h,s,d) flat == (b,s,2048) raw view

#define BM 64
#define BN 64
#define BK 16

// ---------------------------------------------------------------------------
// Kernel 1: proj = x @ w_attn^T + b_attn   (NT GEMM, M=4096 N=6144 K=256)
// ---------------------------------------------------------------------------
__global__ void __launch_bounds__(256) proj_gemm(const float* __restrict__ A,
                                                 const float* __restrict__ B,
                                                 const float* __restrict__ bias) {
    __shared__ __align__(16) float As[BK][BM];
    __shared__ __align__(16) float Bs[BK][BN];
    const int m0 = blockIdx.y * BM, n0 = blockIdx.x * BN;
    const int t = threadIdx.x;
    const int tx = t & 15, ty = t >> 4;
    const int lr = t >> 2, lc = (t & 3) * 4;
    float acc[4][4] = {};
    for (int k0 = 0; k0 < ED; k0 += BK) {
        float4 av = *(const float4*)(A + (size_t)(m0 + lr) * ED + k0 + lc);
        float4 bv = *(const float4*)(B + (size_t)(n0 + lr) * ED + k0 + lc);
        As[lc+0][lr]=av.x; As[lc+1][lr]=av.y; As[lc+2][lr]=av.z; As[lc+3][lr]=av.w;
        Bs[lc+0][lr]=bv.x; Bs[lc+1][lr]=bv.y; Bs[lc+2][lr]=bv.z; Bs[lc+3][lr]=bv.w;
        __syncthreads();
        #pragma unroll
        for (int kk = 0; kk < BK; kk++) {
            float4 a4 = *(const float4*)&As[kk][ty*4];
            float4 b4 = *(const float4*)&Bs[kk][tx*4];
            float ar[4] = {a4.x,a4.y,a4.z,a4.w};
            float br[4] = {b4.x,b4.y,b4.z,b4.w};
            #pragma unroll
            for (int i = 0; i < 4; i++)
                #pragma unroll
                for (int j = 0; j < 4; j++)
                    acc[i][j] = fmaf(ar[i], br[j], acc[i][j]);
        }
        __syncthreads();
    }
    #pragma unroll
    for (int i = 0; i < 4; i++)
        #pragma unroll
        for (int j = 0; j < 4; j++)
            g_proj[(size_t)(m0 + ty*4 + i) * QKV + n0 + tx*4 + j] =
                acc[i][j] + bias[n0 + tx*4 + j];
}

// Raw-view row remap: Q[b,h,s,d] = proj[b, h*128 + s/8, (s%8)*256 + d]
__device__ __forceinline__ int rowoff(int s) { return (s >> 3) * QKV + (s & 7) * ED; }

// ---------------------------------------------------------------------------
// Kernel 2: scores[bh,q,k] = (Q·K)/16 with remapped rows; skip blocks above diag
// ---------------------------------------------------------------------------
__global__ void __launch_bounds__(256) score_gemm() {
    const int q0 = blockIdx.y * BM, k0 = blockIdx.x * BN;
    if (k0 > q0 + (BM - 1)) return;   // fully masked tile
    const int bh = blockIdx.z;
    const int b = bh >> 3, h = bh & 7;
    const float* base = g_proj + (size_t)b * SQL * QKV + (size_t)h * 128 * QKV;
    __shared__ __align__(16) float As[BK][BM];
    __shared__ __align__(16) float Bs[BK][BN];
    const int t = threadIdx.x;
    const int tx = t & 15, ty = t >> 4;
    const int lr = t >> 2, lc = (t & 3) * 4;
    const int ra = rowoff(q0 + lr);          // Q row (chunk offset 0)
    const int rb = rowoff(k0 + lr) + NE;     // K row (chunk offset 2048)
    float acc[4][4] = {};
    for (int d0 = 0; d0 < ED; d0 += BK) {
        float4 av = *(const float4*)(base + ra + d0 + lc);
        float4 bv = *(const float4*)(base + rb + d0 + lc);
        As[lc+0][lr]=av.x; As[lc+1][lr]=av.y; As[lc+2][lr]=av.z; As[lc+3][lr]=av.w;
        Bs[lc+0][lr]=bv.x; Bs[lc+1][lr]=bv.y; Bs[lc+2][lr]=bv.z; Bs[lc+3][lr]=bv.w;
        __syncthreads();
        #pragma unroll
        for (int kk = 0; kk < BK; kk++) {
            float4 a4 = *(const float4*)&As[kk][ty*4];
            float4 b4 = *(const float4*)&Bs[kk][tx*4];
            float ar[4] = {a4.x,a4.y,a4.z,a4.w};
            float br[4] = {b4.x,b4.y,b4.z,b4.w};
            #pragma unroll
            for (int i = 0; i < 4; i++)
                #pragma unroll
                for (int j = 0; j < 4; j++)
                    acc[i][j] = fmaf(ar[i], br[j], acc[i][j]);
        }
        __syncthreads();
    }
    float* S = g_scores + (size_t)bh * SQL * SQL;
    #pragma unroll
    for (int i = 0; i < 4; i++)
        #pragma unroll
        for (int j = 0; j < 4; j++)
            S[(size_t)(q0 + ty*4 + i) * SQL + k0 + tx*4 + j] = acc[i][j] * 0.0625f;
}

// ---------------------------------------------------------------------------
// Kernel 3: causal softmax per row (row = bh*1024 + q), 128 threads/row
// ---------------------------------------------------------------------------
__global__ void __launch_bounds__(128) softmax_rows() {
    const int row = blockIdx.x;
    const int q = row & (SQL - 1);
    float* r = g_scores + (size_t)row * SQL;
    const int t = threadIdx.x;
    float v[8];
    float mx = -1e30f;
    #pragma unroll
    for (int i = 0; i < 8; i++) {
        int k = t + i * 128;
        v[i] = (k <= q) ? r[k] : -1e30f;
        mx = fmaxf(mx, v[i]);
    }
    __shared__ float redm[4], reds[4];
    #pragma unroll
    for (int o = 16; o > 0; o >>= 1) mx = fmaxf(mx, __shfl_xor_sync(0xffffffffu, mx, o));
    if ((t & 31) == 0) redm[t >> 5] = mx;
    __syncthreads();
    mx = fmaxf(fmaxf(redm[0], redm[1]), fmaxf(redm[2], redm[3]));
    float sum = 0.f;
    #pragma unroll
    for (int i = 0; i < 8; i++) {
        int k = t + i * 128;
        v[i] = (k <= q) ? expf(v[i] - mx) : 0.f;
        sum += v[i];
    }
    #pragma unroll
    for (int o = 16; o > 0; o >>= 1) sum += __shfl_xor_sync(0xffffffffu, sum, o);
    if ((t & 31) == 0) reds[t >> 5] = sum;
    __syncthreads();
    sum = reds[0] + reds[1] + reds[2] + reds[3];
    float inv = 1.f / sum;
    #pragma unroll
    for (int i = 0; i < 8; i++) r[t + i * 128] = v[i] * inv;
}

// ---------------------------------------------------------------------------
// Kernel 4: O[bh,q,d] = P @ V  (NN GEMM, causal K-loop truncation)
// ---------------------------------------------------------------------------
__global__ void __launch_bounds__(256) pv_gemm() {
    const int bh = blockIdx.z;
    const int b = bh >> 3, h = bh & 7;
    const int q0 = blockIdx.y * BM;
    const int n0 = blockIdx.x * BN;   // d tile (256 total)
    const float* Sr = g_scores + (size_t)bh * SQL * SQL;
    const float* vbase = g_proj + (size_t)b * SQL * QKV + (size_t)h * 128 * QKV + 2 * NE;
    __shared__ __align__(16) float As[BK][BM];   // P^T tile: [k][q]
    __shared__ __align__(16) float Bs[BK][BN];   // V tile:   [k][d]
    const int t = threadIdx.x;
    const int tx = t & 15, ty = t >> 4;
    const int lrA = t >> 2, lcA = (t & 3) * 4;   // A: 64(q) x 16(k)
    const int lrB = t >> 4, lcB = (t & 15) * 4;  // B: 16(k) x 64(d)
    float acc[4][4] = {};
    const int kend = q0 + BM;                    // P == 0 beyond the diagonal
    for (int k0 = 0; k0 < kend; k0 += BK) {
        float4 av = *(const float4*)(Sr + (size_t)(q0 + lrA) * SQL + k0 + lcA);
        As[lcA+0][lrA]=av.x; As[lcA+1][lrA]=av.y; As[lcA+2][lrA]=av.z; As[lcA+3][lrA]=av.w;
        float4 bv = *(const float4*)(vbase + rowoff(k0 + lrB) + n0 + lcB);
        *(float4*)&Bs[lrB][lcB] = bv;
        __syncthreads();
        #pragma unroll
        for (int kk = 0; kk < BK; kk++) {
            float4 a4 = *(const float4*)&As[kk][ty*4];
            float4 b4 = *(const float4*)&Bs[kk][tx*4];
            float ar[4] = {a4.x,a4.y,a4.z,a4.w};
            float br[4] = {b4.x,b4.y,b4.z,b4.w};
            #pragma unroll
            for (int i = 0; i < 4; i++)
                #pragma unroll
                for (int j = 0; j < 4; j++)
                    acc[i][j] = fmaf(ar[i], br[j], acc[i][j]);
        }
        __syncthreads();
    }
    #pragma unroll
    for (int i = 0; i < 4; i++)
        #pragma unroll
        for (int j = 0; j < 4; j++)
            g_attn[((size_t)bh * SQL + q0 + ty*4 + i) * ED + n0 + tx*4 + j] = acc[i][j];
}

// ---------------------------------------------------------------------------
// Kernel 5: out = attn_flat @ w_out^T + b_out (NT GEMM, M=4096 N=256 K=2048)
// g_attn's (b,h,s,d) layout IS the (b,s,2048) raw view — read it flat.
// ---------------------------------------------------------------------------
__global__ void __launch_bounds__(256) out_gemm(const float* __restrict__ B,
                                                const float* __restrict__ bias,
                                                float* __restrict__ C) {
    __shared__ __align__(16) float As[BK][BM];
    __shared__ __align__(16) float Bs[BK][BN];
    const int m0 = blockIdx.y * BM, n0 = blockIdx.x * BN;
    const int t = threadIdx.x;
    const int tx = t & 15, ty = t >> 4;
    const int lr = t >> 2, lc = (t & 3) * 4;
    float acc[4][4] = {};
    for (int k0 = 0; k0 < NE; k0 += BK) {
        float4 av = *(const float4*)(g_attn + (size_t)(m0 + lr) * NE + k0 + lc);
        float4 bv = *(const float4*)(B + (size_t)(n0 + lr) * NE + k0 + lc);
        As[lc+0][lr]=av.x; As[lc+1][lr]=av.y; As[lc+2][lr]=av.z; As[lc+3][lr]=av.w;
        Bs[lc+0][lr]=bv.x; Bs[lc+1][lr]=bv.y; Bs[lc+2][lr]=bv.z; Bs[lc+3][lr]=bv.w;
        __syncthreads();
        #pragma unroll
        for (int kk = 0; kk < BK; kk++) {
            float4 a4 = *(const float4*)&As[kk][ty*4];
            float4 b4 = *(const float4*)&Bs[kk][tx*4];
            float ar[4] = {a4.x,a4.y,a4.z,a4.w};
            float br[4] = {b4.x,b4.y,b4.z,b4.w};
            #pragma unroll
            for (int i = 0; i < 4; i++)
                #pragma unroll
                for (int j = 0; j < 4; j++)
                    acc[i][j] = fmaf(ar[i], br[j], acc[i][j]);
        }
        __syncthreads();
    }
    #pragma unroll
    for (int i = 0; i < 4; i++)
        #pragma unroll
        for (int j = 0; j < 4; j++)
            C[(size_t)(m0 + ty*4 + i) * ED + n0 + tx*4 + j] =
                acc[i][j] + bias[n0 + tx*4 + j];
}

extern "C" void kernel_launch(void* const* d_in, const int* in_sizes, int n_in,
                              void* d_out, int out_size) {
    const float* x      = (const float*)d_in[0];
    const float* w_attn = (const float*)d_in[1];
    const float* b_attn = (const float*)d_in[2];
    const float* w_out  = (const float*)d_in[3];
    const float* b_out  = (const float*)d_in[4];
    float* out = (float*)d_out;

    proj_gemm<<<dim3(QKV / BN, TOK / BM), 256>>>(x, w_attn, b_attn);
    score_gemm<<<dim3(SQL / BN, SQL / BM, BSZ * NHH), 256>>>();
    softmax_rows<<<BSZ * NHH * SQL, 128>>>();
    pv_gemm<<<dim3(ED / BN, SQL / BM, BSZ * NHH), 256>>>();
    out_gemm<<<dim3(ED / BN, TOK / BM), 256>>>(w_out, b_out, out);
}

// round 2
// speedup vs baseline: 1.0913x; 1.0913x over previous
#include <cuda_runtime.h>
#include <math.h>

#define NHH 8
#define ED 256
#define SQL 1024
#define BSZ 4
#define QKV (NHH*3*ED)   /* 6144 */
#define NE  (NHH*ED)     /* 2048 */
#define TOK (BSZ*SQL)    /* 4096 */

// Scratch (device globals; allocation-free per harness rules)
__device__ float g_proj[(size_t)TOK*QKV];          // (b, s, 6144)
__device__ float g_scores[(size_t)BSZ*NHH*SQL*SQL];// (bh, q, k)
__device__ float g_attn[(size_t)TOK*NE];           // (b,h,s,d) flat == (b,s,2048) raw view

#define BM 128
#define BN 128
#define BK 8

typedef unsigned long long ull;

// Raw-view row remap: Q[b,h,s,d] lives at proj row (h*128 + s/8), col (s%8)*256 + d
__device__ __forceinline__ size_t rowadr(int s) {
    return (size_t)(s >> 3) * QKV + (size_t)(s & 7) * ED;
}

// ---------------------------------------------------------------------------
// 8x8 microtile FMA step over one BK slice, using packed fma.rn.f32x2
// acc[i][j] holds output columns (2j, 2j+1) for row i.
// ---------------------------------------------------------------------------
__device__ __forceinline__ void mm_step(const float (*As)[BM], const float (*Bs)[BN],
                                        int ty8, int tx8, ull acc[8][4]) {
    #pragma unroll
    for (int kk = 0; kk < BK; kk++) {
        float a[8];
        *(float4*)&a[0] = *(const float4*)&As[kk][ty8];
        *(float4*)&a[4] = *(const float4*)&As[kk][ty8 + 4];
        ull b2[4];
        *(float4*)&b2[0] = *(const float4*)&Bs[kk][tx8];      // pairs (b0,b1),(b2,b3)
        *(float4*)&b2[2] = *(const float4*)&Bs[kk][tx8 + 4];  // pairs (b4,b5),(b6,b7)
        #pragma unroll
        for (int i = 0; i < 8; i++) {
            ull a2;
            unsigned int ar = __float_as_uint(a[i]);
            asm("mov.b64 %0, {%1, %2};" : "=l"(a2) : "r"(ar), "r"(ar));
            #pragma unroll
            for (int j = 0; j < 4; j++)
                asm("fma.rn.f32x2 %0, %1, %2, %0;" : "+l"(acc[i][j]) : "l"(a2), "l"(b2[j]));
        }
    }
}

__device__ __forceinline__ void unpack_row(const ull acc[4], float o[8]) {
    #pragma unroll
    for (int j = 0; j < 4; j++) {
        unsigned int lo, hi;
        asm("mov.b64 {%0, %1}, %2;" : "=r"(lo), "=r"(hi) : "l"(acc[j]));
        o[2*j]   = __uint_as_float(lo);
        o[2*j+1] = __uint_as_float(hi);
    }
}

// ---------------------------------------------------------------------------
// Kernel 1: proj = x @ w_attn^T + b_attn   (NT, M=4096 N=6144 K=256)
// ---------------------------------------------------------------------------
__global__ void __launch_bounds__(256) proj_gemm(const float* __restrict__ A,
                                                 const float* __restrict__ B,
                                                 const float* __restrict__ bias) {
    __shared__ __align__(16) float As[2][BK][BM];
    __shared__ __align__(16) float Bs[2][BK][BN];
    const int m0 = blockIdx.y * BM, n0 = blockIdx.x * BN;
    const int t = threadIdx.x;
    const int tx8 = (t & 15) * 8, ty8 = (t >> 4) * 8;
    const int lr = t >> 1, lc = (t & 1) * 4;
    const int NS = ED / BK;
    ull acc[8][4] = {};

    float4 av = *(const float4*)(A + (size_t)(m0 + lr) * ED + lc);
    float4 bv = *(const float4*)(B + (size_t)(n0 + lr) * ED + lc);
    #pragma unroll
    for (int j = 0; j < 4; j++) { As[0][lc+j][lr] = ((float*)&av)[j]; Bs[0][lc+j][lr] = ((float*)&bv)[j]; }
    __syncthreads();

    int buf = 0;
    for (int s = 0; s < NS; s++) {
        float4 an, bn;
        if (s + 1 < NS) {
            an = *(const float4*)(A + (size_t)(m0 + lr) * ED + (s+1)*BK + lc);
            bn = *(const float4*)(B + (size_t)(n0 + lr) * ED + (s+1)*BK + lc);
        }
        mm_step(As[buf], Bs[buf], ty8, tx8, acc);
        if (s + 1 < NS) {
            #pragma unroll
            for (int j = 0; j < 4; j++) { As[buf^1][lc+j][lr] = ((float*)&an)[j]; Bs[buf^1][lc+j][lr] = ((float*)&bn)[j]; }
        }
        __syncthreads();
        buf ^= 1;
    }

    float breg[8];
    *(float4*)&breg[0] = *(const float4*)(bias + n0 + tx8);
    *(float4*)&breg[4] = *(const float4*)(bias + n0 + tx8 + 4);
    #pragma unroll
    for (int i = 0; i < 8; i++) {
        float o[8]; unpack_row(acc[i], o);
        #pragma unroll
        for (int j = 0; j < 8; j++) o[j] += breg[j];
        float* dst = g_proj + (size_t)(m0 + ty8 + i) * QKV + n0 + tx8;
        *(float4*)dst = *(float4*)&o[0];
        *(float4*)(dst + 4) = *(float4*)&o[4];
    }
}

// ---------------------------------------------------------------------------
// Kernel 2: scores = (Q·K^T)/16 per (b,h); skip tiles fully above diagonal
// ---------------------------------------------------------------------------
__global__ void __launch_bounds__(256) score_gemm() {
    const int q0 = blockIdx.y * BM, k0 = blockIdx.x * BN;
    if (k0 > q0) return;                       // fully masked tile
    const int bh = blockIdx.z;
    const int b = bh >> 3, h = bh & 7;
    const float* base = g_proj + (size_t)b * SQL * QKV + (size_t)h * 128 * QKV;
    __shared__ __align__(16) float As[2][BK][BM];
    __shared__ __align__(16) float Bs[2][BK][BN];
    const int t = threadIdx.x;
    const int tx8 = (t & 15) * 8, ty8 = (t >> 4) * 8;
    const int lr = t >> 1, lc = (t & 1) * 4;
    const size_t ra = rowadr(q0 + lr);         // Q chunk (offset 0)
    const size_t rb = rowadr(k0 + lr) + NE;    // K chunk (offset 2048)
    const int NS = ED / BK;
    ull acc[8][4] = {};

    float4 av = *(const float4*)(base + ra + lc);
    float4 bv = *(const float4*)(base + rb + lc);
    #pragma unroll
    for (int j = 0; j < 4; j++) { As[0][lc+j][lr] = ((float*)&av)[j]; Bs[0][lc+j][lr] = ((float*)&bv)[j]; }
    __syncthreads();

    int buf = 0;
    for (int s = 0; s < NS; s++) {
        float4 an, bn;
        if (s + 1 < NS) {
            an = *(const float4*)(base + ra + (s+1)*BK + lc);
            bn = *(const float4*)(base + rb + (s+1)*BK + lc);
        }
        mm_step(As[buf], Bs[buf], ty8, tx8, acc);
        if (s + 1 < NS) {
            #pragma unroll
            for (int j = 0; j < 4; j++) { As[buf^1][lc+j][lr] = ((float*)&an)[j]; Bs[buf^1][lc+j][lr] = ((float*)&bn)[j]; }
        }
        __syncthreads();
        buf ^= 1;
    }

    float* S = g_scores + (size_t)bh * SQL * SQL;
    #pragma unroll
    for (int i = 0; i < 8; i++) {
        float o[8]; unpack_row(acc[i], o);
        #pragma unroll
        for (int j = 0; j < 8; j++) o[j] *= 0.0625f;
        float* dst = S + (size_t)(q0 + ty8 + i) * SQL + k0 + tx8;
        *(float4*)dst = *(float4*)&o[0];
        *(float4*)(dst + 4) = *(float4*)&o[4];
    }
}

// ---------------------------------------------------------------------------
// Kernel 3: causal softmax per row (row = bh*1024 + q), 128 threads/row
// ---------------------------------------------------------------------------
__global__ void __launch_bounds__(128) softmax_rows() {
    const int row = blockIdx.x;
    const int q = row & (SQL - 1);
    float* r = g_scores + (size_t)row * SQL;
    const int t = threadIdx.x;
    float v[8];
    float mx = -1e30f;
    #pragma unroll
    for (int i = 0; i < 8; i++) {
        int k = t + i * 128;
        v[i] = (k <= q) ? r[k] : -1e30f;
        mx = fmaxf(mx, v[i]);
    }
    __shared__ float redm[4], reds[4];
    #pragma unroll
    for (int o = 16; o > 0; o >>= 1) mx = fmaxf(mx, __shfl_xor_sync(0xffffffffu, mx, o));
    if ((t & 31) == 0) redm[t >> 5] = mx;
    __syncthreads();
    mx = fmaxf(fmaxf(redm[0], redm[1]), fmaxf(redm[2], redm[3]));
    float sum = 0.f;
    #pragma unroll
    for (int i = 0; i < 8; i++) {
        int k = t + i * 128;
        v[i] = (k <= q) ? expf(v[i] - mx) : 0.f;
        sum += v[i];
    }
    #pragma unroll
    for (int o = 16; o > 0; o >>= 1) sum += __shfl_xor_sync(0xffffffffu, sum, o);
    if ((t & 31) == 0) reds[t >> 5] = sum;
    __syncthreads();
    sum = reds[0] + reds[1] + reds[2] + reds[3];
    float inv = 1.f / sum;
    #pragma unroll
    for (int i = 0; i < 8; i++) r[t + i * 128] = v[i] * inv;
}

// ---------------------------------------------------------------------------
// Kernel 4: O = P @ V  (NN, causal K-loop truncation)
// ---------------------------------------------------------------------------
__global__ void __launch_bounds__(256) pv_gemm() {
    const int bh = blockIdx.z;
    const int b = bh >> 3, h = bh & 7;
    const int q0 = blockIdx.y * BM;
    const int n0 = blockIdx.x * BN;   // d tile
    const float* Sr = g_scores + (size_t)bh * SQL * SQL;
    const float* vbase = g_proj + (size_t)b * SQL * QKV + (size_t)h * 128 * QKV + 2 * NE;
    __shared__ __align__(16) float As[2][BK][BM];
    __shared__ __align__(16) float Bs[2][BK][BN];
    const int t = threadIdx.x;
    const int tx8 = (t & 15) * 8, ty8 = (t >> 4) * 8;
    const int lrA = t >> 1, lcA = (t & 1) * 4;   // P: 128(q) x 8(k), transposed store
    const int krB = t >> 5, dcB = (t & 31) * 4;  // V: 8(k) x 128(d), direct store
    const int NS = (q0 + BM) / BK;               // P == 0 beyond diagonal
    ull acc[8][4] = {};

    float4 av = *(const float4*)(Sr + (size_t)(q0 + lrA) * SQL + lcA);
    float4 bv = *(const float4*)(vbase + rowadr(krB) + n0 + dcB);
    #pragma unroll
    for (int j = 0; j < 4; j++) As[0][lcA+j][lrA] = ((float*)&av)[j];
    *(float4*)&Bs[0][krB][dcB] = bv;
    __syncthreads();

    int buf = 0;
    for (int s = 0; s < NS; s++) {
        float4 an, bn;
        if (s + 1 < NS) {
            an = *(const float4*)(Sr + (size_t)(q0 + lrA) * SQL + (s+1)*BK + lcA);
            bn = *(const float4*)(vbase + rowadr((s+1)*BK + krB) + n0 + dcB);
        }
        mm_step(As[buf], Bs[buf], ty8, tx8, acc);
        if (s + 1 < NS) {
            #pragma unroll
            for (int j = 0; j < 4; j++) As[buf^1][lcA+j][lrA] = ((float*)&an)[j];
            *(float4*)&Bs[buf^1][krB][dcB] = bn;
        }
        __syncthreads();
        buf ^= 1;
    }

    #pragma unroll
    for (int i = 0; i < 8; i++) {
        float o[8]; unpack_row(acc[i], o);
        float* dst = g_attn + ((size_t)bh * SQL + q0 + ty8 + i) * ED + n0 + tx8;
        *(float4*)dst = *(float4*)&o[0];
        *(float4*)(dst + 4) = *(float4*)&o[4];
    }
}

// ---------------------------------------------------------------------------
// Kernel 5: out = attn_flat @ w_out^T + b_out (NT, M=4096 N=256 K=2048)
// ---------------------------------------------------------------------------
__global__ void __launch_bounds__(256) out_gemm(const float* __restrict__ B,
                                                const float* __restrict__ bias,
                                                float* __restrict__ C) {
    __shared__ __align__(16) float As[2][BK][BM];
    __shared__ __align__(16) float Bs[2][BK][BN];
    const int m0 = blockIdx.y * BM, n0 = blockIdx.x * BN;
    const int t = threadIdx.x;
    const int tx8 = (t & 15) * 8, ty8 = (t >> 4) * 8;
    const int lr = t >> 1, lc = (t & 1) * 4;
    const int NS = NE / BK;
    ull acc[8][4] = {};

    float4 av = *(const float4*)(g_attn + (size_t)(m0 + lr) * NE + lc);
    float4 bv = *(const float4*)(B + (size_t)(n0 + lr) * NE + lc);
    #pragma unroll
    for (int j = 0; j < 4; j++) { As[0][lc+j][lr] = ((float*)&av)[j]; Bs[0][lc+j][lr] = ((float*)&bv)[j]; }
    __syncthreads();

    int buf = 0;
    for (int s = 0; s < NS; s++) {
        float4 an, bn;
        if (s + 1 < NS) {
            an = *(const float4*)(g_attn + (size_t)(m0 + lr) * NE + (s+1)*BK + lc);
            bn = *(const float4*)(B + (size_t)(n0 + lr) * NE + (s+1)*BK + lc);
        }
        mm_step(As[buf], Bs[buf], ty8, tx8, acc);
        if (s + 1 < NS) {
            #pragma unroll
            for (int j = 0; j < 4; j++) { As[buf^1][lc+j][lr] = ((float*)&an)[j]; Bs[buf^1][lc+j][lr] = ((float*)&bn)[j]; }
        }
        __syncthreads();
        buf ^= 1;
    }

    float breg[8];
    *(float4*)&breg[0] = *(const float4*)(bias + n0 + tx8);
    *(float4*)&breg[4] = *(const float4*)(bias + n0 + tx8 + 4);
    #pragma unroll
    for (int i = 0; i < 8; i++) {
        float o[8]; unpack_row(acc[i], o);
        #pragma unroll
        for (int j = 0; j < 8; j++) o[j] += breg[j];
        float* dst = C + (size_t)(m0 + ty8 + i) * ED + n0 + tx8;
        *(float4*)dst = *(float4*)&o[0];
        *(float4*)(dst + 4) = *(float4*)&o[4];
    }
}

extern "C" void kernel_launch(void* const* d_in, const int* in_sizes, int n_in,
                              void* d_out, int out_size) {
    const float* x      = (const float*)d_in[0];
    const float* w_attn = (const float*)d_in[1];
    const float* b_attn = (const float*)d_in[2];
    const float* w_out  = (const float*)d_in[3];
    const float* b_out  = (const float*)d_in[4];
    float* out = (float*)d_out;

    proj_gemm<<<dim3(QKV / BN, TOK / BM), 256>>>(x, w_attn, b_attn);
    score_gemm<<<dim3(SQL / BN, SQL / BM, BSZ * NHH), 256>>>();
    softmax_rows<<<BSZ * NHH * SQL, 128>>>();
    pv_gemm<<<dim3(ED / BN, SQL / BM, BSZ * NHH), 256>>>();
    out_gemm<<<dim3(ED / BN, TOK / BM), 256>>>(w_out, b_out, out);
}

// round 3
// speedup vs baseline: 1.9311x; 1.7695x over previous
#include <cuda_runtime.h>
#include <cuda_bf16.h>
#include <math.h>
#include <stdint.h>

#define NHH 8
#define ED 256
#define SQL 1024
#define BSZ 4
#define QKV (NHH*3*ED)   /* 6144 */
#define NE  (NHH*ED)     /* 2048 */
#define TOK (BSZ*SQL)    /* 4096 */

// Scratch (device globals; allocation-free per harness rules)
__device__ float g_proj[(size_t)TOK*QKV];          // (b, s, 6144)
__device__ float g_scores[(size_t)BSZ*NHH*SQL*SQL];// (bh, q, k)
__device__ float g_attn[(size_t)TOK*NE];           // (b,h,s,d) flat == (b,s,2048) raw view

#define BM 128
#define BN 128
#define BK 16          /* one m16n8k16 k-chunk per stage */
#define STRIDE 12      /* uint32 words per smem row (8 used + pad): conflict-free */

// Raw-view row remap: head-local seq row s lives at proj row (s/8), col (s%8)*256
__device__ __forceinline__ size_t rowadr(int s) {
    return (size_t)(s >> 3) * QKV + (size_t)(s & 7) * ED;
}

// split fp32 pair (a,b adjacent in k) into packed bf16x2 hi and lo words
__device__ __forceinline__ void split2(float a, float b, unsigned &h, unsigned &l) {
    __nv_bfloat16 ah = __float2bfloat16(a), bh = __float2bfloat16(b);
    float ar = a - __bfloat162float(ah);
    float br = b - __bfloat162float(bh);
    __nv_bfloat16 al = __float2bfloat16(ar), bl = __float2bfloat16(br);
    h = (unsigned)__bfloat16_as_ushort(ah) | ((unsigned)__bfloat16_as_ushort(bh) << 16);
    l = (unsigned)__bfloat16_as_ushort(al) | ((unsigned)__bfloat16_as_ushort(bl) << 16);
}

// store 8 consecutive-k floats (2 float4) of one row into hi/lo smem tiles
__device__ __forceinline__ void store_split(unsigned* H, unsigned* L, int row, int half,
                                            float4 v0, float4 v1) {
    unsigned h0,l0,h1,l1,h2,l2,h3,l3;
    split2(v0.x, v0.y, h0, l0);
    split2(v0.z, v0.w, h1, l1);
    split2(v1.x, v1.y, h2, l2);
    split2(v1.z, v1.w, h3, l3);
    *(uint4*)&H[row*STRIDE + half*4] = make_uint4(h0,h1,h2,h3);
    *(uint4*)&L[row*STRIDE + half*4] = make_uint4(l0,l1,l2,l3);
}

#define MMA_BF16(C, A0, A1, A2, A3, B0, B1)                                      \
    asm volatile("mma.sync.aligned.m16n8k16.row.col.f32.bf16.bf16.f32 "          \
        "{%0,%1,%2,%3}, {%4,%5,%6,%7}, {%8,%9}, {%0,%1,%2,%3};"                  \
        : "+f"((C)[0]), "+f"((C)[1]), "+f"((C)[2]), "+f"((C)[3])                  \
        : "r"(A0), "r"(A1), "r"(A2), "r"(A3), "r"(B0), "r"(B1))

// One BK=16 stage: 8 warps as 4(m) x 2(n); warp tile 32(m) x 64(n).
// 3 MMAs per tile pair: hi*hi + hi*lo + lo*hi (split-bf16 fp32 emulation).
__device__ __forceinline__ void compute_stage(
    const unsigned* __restrict__ Ah, const unsigned* __restrict__ Al,
    const unsigned* __restrict__ Bh, const unsigned* __restrict__ Bl,
    int wm, int wn, int lane, float acc[2][8][4])
{
    const int g = lane >> 2, q = lane & 3;
    unsigned ah[2][4], al[2][4];
    #pragma unroll
    for (int mt = 0; mt < 2; mt++) {
        int r0 = wm*32 + mt*16 + g;
        ah[mt][0] = Ah[r0*STRIDE + q];      ah[mt][1] = Ah[(r0+8)*STRIDE + q];
        ah[mt][2] = Ah[r0*STRIDE + q + 4];  ah[mt][3] = Ah[(r0+8)*STRIDE + q + 4];
        al[mt][0] = Al[r0*STRIDE + q];      al[mt][1] = Al[(r0+8)*STRIDE + q];
        al[mt][2] = Al[r0*STRIDE + q + 4];  al[mt][3] = Al[(r0+8)*STRIDE + q + 4];
    }
    #pragma unroll
    for (int nt = 0; nt < 8; nt++) {
        int n = wn*64 + nt*8 + g;
        unsigned bh0 = Bh[n*STRIDE + q], bh1 = Bh[n*STRIDE + q + 4];
        unsigned bl0 = Bl[n*STRIDE + q], bl1 = Bl[n*STRIDE + q + 4];
        #pragma unroll
        for (int mt = 0; mt < 2; mt++) {
            MMA_BF16(acc[mt][nt], ah[mt][0], ah[mt][1], ah[mt][2], ah[mt][3], bh0, bh1);
            MMA_BF16(acc[mt][nt], ah[mt][0], ah[mt][1], ah[mt][2], ah[mt][3], bl0, bl1);
            MMA_BF16(acc[mt][nt], al[mt][0], al[mt][1], al[mt][2], al[mt][3], bh0, bh1);
        }
    }
}

#define SMEM_DECL                                                                 \
    __shared__ __align__(16) unsigned sAh[2][BM*STRIDE], sAl[2][BM*STRIDE];       \
    __shared__ __align__(16) unsigned sBh[2][BN*STRIDE], sBl[2][BN*STRIDE]

// ---------------------------------------------------------------------------
// Kernel 1: proj = x @ w_attn^T + b_attn  (NT, M=4096 N=6144 K=256)
// ---------------------------------------------------------------------------
__global__ void __launch_bounds__(256) proj_gemm(const float* __restrict__ A,
                                                 const float* __restrict__ B,
                                                 const float* __restrict__ bias) {
    SMEM_DECL;
    const int m0 = blockIdx.y * BM, n0 = blockIdx.x * BN;
    const int t = threadIdx.x, lane = t & 31, w = t >> 5;
    const int wm = w >> 1, wn = w & 1;
    const int lr = t >> 1, half = t & 1;
    const float* aptr = A + (size_t)(m0 + lr) * ED + half*8;
    const float* bptr = B + (size_t)(n0 + lr) * ED + half*8;
    const int NS = ED / BK;
    float acc[2][8][4] = {};

    float4 a0 = *(const float4*)aptr, a1 = *(const float4*)(aptr + 4);
    float4 b0 = *(const float4*)bptr, b1 = *(const float4*)(bptr + 4);
    store_split(sAh[0], sAl[0], lr, half, a0, a1);
    store_split(sBh[0], sBl[0], lr, half, b0, b1);
    __syncthreads();

    int buf = 0;
    for (int s = 0; s < NS; s++) {
        if (s + 1 < NS) {
            a0 = *(const float4*)(aptr + (s+1)*BK);
            a1 = *(const float4*)(aptr + (s+1)*BK + 4);
            b0 = *(const float4*)(bptr + (s+1)*BK);
            b1 = *(const float4*)(bptr + (s+1)*BK + 4);
        }
        compute_stage(sAh[buf], sAl[buf], sBh[buf], sBl[buf], wm, wn, lane, acc);
        if (s + 1 < NS) {
            store_split(sAh[buf^1], sAl[buf^1], lr, half, a0, a1);
            store_split(sBh[buf^1], sBl[buf^1], lr, half, b0, b1);
        }
        __syncthreads();
        buf ^= 1;
    }

    const int g = lane >> 2, q = lane & 3;
    #pragma unroll
    for (int mt = 0; mt < 2; mt++) {
        int row = m0 + wm*32 + mt*16 + g;
        #pragma unroll
        for (int nt = 0; nt < 8; nt++) {
            int col = n0 + wn*64 + nt*8 + q*2;
            float bv0 = bias[col], bv1 = bias[col+1];
            float* d0 = g_proj + (size_t)row * QKV + col;
            float* d1 = g_proj + (size_t)(row+8) * QKV + col;
            *(float2*)d0 = make_float2(acc[mt][nt][0] + bv0, acc[mt][nt][1] + bv1);
            *(float2*)d1 = make_float2(acc[mt][nt][2] + bv0, acc[mt][nt][3] + bv1);
        }
    }
}

// ---------------------------------------------------------------------------
// Kernel 2: scores = (Q·K^T)/16 per (b,h); skip tiles fully above diagonal
// ---------------------------------------------------------------------------
__global__ void __launch_bounds__(256) score_gemm() {
    const int q0 = blockIdx.y * BM, k0 = blockIdx.x * BN;
    if (k0 > q0) return;
    const int bh = blockIdx.z;
    const int b = bh >> 3, h = bh & 7;
    const float* base = g_proj + (size_t)b * SQL * QKV + (size_t)h * 128 * QKV;
    SMEM_DECL;
    const int t = threadIdx.x, lane = t & 31, w = t >> 5;
    const int wm = w >> 1, wn = w & 1;
    const int lr = t >> 1, half = t & 1;
    const float* aptr = base + rowadr(q0 + lr) + half*8;        // Q chunk
    const float* bptr = base + rowadr(k0 + lr) + NE + half*8;   // K chunk
    const int NS = ED / BK;
    float acc[2][8][4] = {};

    float4 a0 = *(const float4*)aptr, a1 = *(const float4*)(aptr + 4);
    float4 b0 = *(const float4*)bptr, b1 = *(const float4*)(bptr + 4);
    store_split(sAh[0], sAl[0], lr, half, a0, a1);
    store_split(sBh[0], sBl[0], lr, half, b0, b1);
    __syncthreads();

    int buf = 0;
    for (int s = 0; s < NS; s++) {
        if (s + 1 < NS) {
            a0 = *(const float4*)(aptr + (s+1)*BK);
            a1 = *(const float4*)(aptr + (s+1)*BK + 4);
            b0 = *(const float4*)(bptr + (s+1)*BK);
            b1 = *(const float4*)(bptr + (s+1)*BK + 4);
        }
        compute_stage(sAh[buf], sAl[buf], sBh[buf], sBl[buf], wm, wn, lane, acc);
        if (s + 1 < NS) {
            store_split(sAh[buf^1], sAl[buf^1], lr, half, a0, a1);
            store_split(sBh[buf^1], sBl[buf^1], lr, half, b0, b1);
        }
        __syncthreads();
        buf ^= 1;
    }

    float* S = g_scores + (size_t)bh * SQL * SQL;
    const int g = lane >> 2, q = lane & 3;
    #pragma unroll
    for (int mt = 0; mt < 2; mt++) {
        int row = q0 + wm*32 + mt*16 + g;
        #pragma unroll
        for (int nt = 0; nt < 8; nt++) {
            int col = k0 + wn*64 + nt*8 + q*2;
            float* d0 = S + (size_t)row * SQL + col;
            float* d1 = S + (size_t)(row+8) * SQL + col;
            *(float2*)d0 = make_float2(acc[mt][nt][0]*0.0625f, acc[mt][nt][1]*0.0625f);
            *(float2*)d1 = make_float2(acc[mt][nt][2]*0.0625f, acc[mt][nt][3]*0.0625f);
        }
    }
}

// ---------------------------------------------------------------------------
// Kernel 3: causal softmax per row (row = bh*1024 + q)
// ---------------------------------------------------------------------------
__global__ void __launch_bounds__(128) softmax_rows() {
    const int row = blockIdx.x;
    const int q = row & (SQL - 1);
    float* r = g_scores + (size_t)row * SQL;
    const int t = threadIdx.x;
    float v[8];
    float mx = -1e30f;
    #pragma unroll
    for (int i = 0; i < 8; i++) {
        int k = t + i * 128;
        v[i] = (k <= q) ? r[k] : -1e30f;
        mx = fmaxf(mx, v[i]);
    }
    __shared__ float redm[4], reds[4];
    #pragma unroll
    for (int o = 16; o > 0; o >>= 1) mx = fmaxf(mx, __shfl_xor_sync(0xffffffffu, mx, o));
    if ((t & 31) == 0) redm[t >> 5] = mx;
    __syncthreads();
    mx = fmaxf(fmaxf(redm[0], redm[1]), fmaxf(redm[2], redm[3]));
    float sum = 0.f;
    #pragma unroll
    for (int i = 0; i < 8; i++) {
        int k = t + i * 128;
        v[i] = (k <= q) ? expf(v[i] - mx) : 0.f;
        sum += v[i];
    }
    #pragma unroll
    for (int o = 16; o > 0; o >>= 1) sum += __shfl_xor_sync(0xffffffffu, sum, o);
    if ((t & 31) == 0) reds[t >> 5] = sum;
    __syncthreads();
    sum = reds[0] + reds[1] + reds[2] + reds[3];
    float inv = 1.f / sum;
    #pragma unroll
    for (int i = 0; i < 8; i++) r[t + i * 128] = v[i] * inv;
}

// ---------------------------------------------------------------------------
// Kernel 4: O = P @ V  (NN, causal K-loop truncation). V transposed at load.
// ---------------------------------------------------------------------------
__global__ void __launch_bounds__(256) pv_gemm() {
    const int bh = blockIdx.z;
    const int b = bh >> 3, h = bh & 7;
    const int q0 = blockIdx.y * BM;
    const int n0 = blockIdx.x * BN;   // d tile
    const float* Sr = g_scores + (size_t)bh * SQL * SQL;
    const float* vbase = g_proj + (size_t)b * SQL * QKV + (size_t)h * 128 * QKV + 2 * NE;
    SMEM_DECL;
    const int t = threadIdx.x, lane = t & 31, w = t >> 5;
    const int wm = w >> 1, wn = w & 1;
    const int lr = t >> 1, half = t & 1;             // P loader: row lr, k-half
    const int kp = t & 7, d4 = t >> 3;               // V loader: kpair 0..7, d-quad 0..31
    const int NS = (q0 + BM) / BK;
    float acc[2][8][4] = {};

    // prologue
    {
        float4 a0 = *(const float4*)(Sr + (size_t)(q0+lr)*SQL + half*8);
        float4 a1 = *(const float4*)(Sr + (size_t)(q0+lr)*SQL + half*8 + 4);
        store_split(sAh[0], sAl[0], lr, half, a0, a1);
        float4 v0 = *(const float4*)(vbase + rowadr(2*kp)     + n0 + d4*4);
        float4 v1 = *(const float4*)(vbase + rowadr(2*kp + 1) + n0 + d4*4);
        #pragma unroll
        for (int j = 0; j < 4; j++) {
            unsigned hh, ll;
            split2(((const float*)&v0)[j], ((const float*)&v1)[j], hh, ll);
            sBh[0][(d4*4 + j)*STRIDE + kp] = hh;
            sBl[0][(d4*4 + j)*STRIDE + kp] = ll;
        }
    }
    __syncthreads();

    int buf = 0;
    for (int s = 0; s < NS; s++) {
        float4 a0, a1, v0, v1;
        if (s + 1 < NS) {
            int kb = (s+1) * BK;
            a0 = *(const float4*)(Sr + (size_t)(q0+lr)*SQL + kb + half*8);
            a1 = *(const float4*)(Sr + (size_t)(q0+lr)*SQL + kb + half*8 + 4);
            v0 = *(const float4*)(vbase + rowadr(kb + 2*kp)     + n0 + d4*4);
            v1 = *(const float4*)(vbase + rowadr(kb + 2*kp + 1) + n0 + d4*4);
        }
        compute_stage(sAh[buf], sAl[buf], sBh[buf], sBl[buf], wm, wn, lane, acc);
        if (s + 1 < NS) {
            store_split(sAh[buf^1], sAl[buf^1], lr, half, a0, a1);
            #pragma unroll
            for (int j = 0; j < 4; j++) {
                unsigned hh, ll;
                split2(((const float*)&v0)[j], ((const float*)&v1)[j], hh, ll);
                sBh[buf^1][(d4*4 + j)*STRIDE + kp] = hh;
                sBl[buf^1][(d4*4 + j)*STRIDE + kp] = ll;
            }
        }
        __syncthreads();
        buf ^= 1;
    }

    const int g = lane >> 2, q = lane & 3;
    #pragma unroll
    for (int mt = 0; mt < 2; mt++) {
        int row = q0 + wm*32 + mt*16 + g;
        #pragma unroll
        for (int nt = 0; nt < 8; nt++) {
            int col = n0 + wn*64 + nt*8 + q*2;
            float* d0 = g_attn + ((size_t)bh * SQL + row) * ED + col;
            float* d1 = g_attn + ((size_t)bh * SQL + row + 8) * ED + col;
            *(float2*)d0 = make_float2(acc[mt][nt][0], acc[mt][nt][1]);
            *(float2*)d1 = make_float2(acc[mt][nt][2], acc[mt][nt][3]);
        }
    }
}

// ---------------------------------------------------------------------------
// Kernel 5: out = attn_flat @ w_out^T + b_out (NT, M=4096 N=256 K=2048)
// ---------------------------------------------------------------------------
__global__ void __launch_bounds__(256) out_gemm(const float* __restrict__ B,
                                                const float* __restrict__ bias,
                                                float* __restrict__ C) {
    SMEM_DECL;
    const int m0 = blockIdx.y * BM, n0 = blockIdx.x * BN;
    const int t = threadIdx.x, lane = t & 31, w = t >> 5;
    const int wm = w >> 1, wn = w & 1;
    const int lr = t >> 1, half = t & 1;
    const float* aptr = g_attn + (size_t)(m0 + lr) * NE + half*8;
    const float* bptr = B + (size_t)(n0 + lr) * NE + half*8;
    const int NS = NE / BK;
    float acc[2][8][4] = {};

    float4 a0 = *(const float4*)aptr, a1 = *(const float4*)(aptr + 4);
    float4 b0 = *(const float4*)bptr, b1 = *(const float4*)(bptr + 4);
    store_split(sAh[0], sAl[0], lr, half, a0, a1);
    store_split(sBh[0], sBl[0], lr, half, b0, b1);
    __syncthreads();

    int buf = 0;
    for (int s = 0; s < NS; s++) {
        if (s + 1 < NS) {
            a0 = *(const float4*)(aptr + (s+1)*BK);
            a1 = *(const float4*)(aptr + (s+1)*BK + 4);
            b0 = *(const float4*)(bptr + (s+1)*BK);
            b1 = *(const float4*)(bptr + (s+1)*BK + 4);
        }
        compute_stage(sAh[buf], sAl[buf], sBh[buf], sBl[buf], wm, wn, lane, acc);
        if (s + 1 < NS) {
            store_split(sAh[buf^1], sAl[buf^1], lr, half, a0, a1);
            store_split(sBh[buf^1], sBl[buf^1], lr, half, b0, b1);
        }
        __syncthreads();
        buf ^= 1;
    }

    const int g = lane >> 2, q = lane & 3;
    #pragma unroll
    for (int mt = 0; mt < 2; mt++) {
        int row = m0 + wm*32 + mt*16 + g;
        #pragma unroll
        for (int nt = 0; nt < 8; nt++) {
            int col = n0 + wn*64 + nt*8 + q*2;
            float bv0 = bias[col], bv1 = bias[col+1];
            float* d0 = C + (size_t)row * ED + col;
            float* d1 = C + (size_t)(row+8) * ED + col;
            *(float2*)d0 = make_float2(acc[mt][nt][0] + bv0, acc[mt][nt][1] + bv1);
            *(float2*)d1 = make_float2(acc[mt][nt][2] + bv0, acc[mt][nt][3] + bv1);
        }
    }
}

extern "C" void kernel_launch(void* const* d_in, const int* in_sizes, int n_in,
                              void* d_out, int out_size) {
    const float* x      = (const float*)d_in[0];
    const float* w_attn = (const float*)d_in[1];
    const float* b_attn = (const float*)d_in[2];
    const float* w_out  = (const float*)d_in[3];
    const float* b_out  = (const float*)d_in[4];
    float* out = (float*)d_out;

    proj_gemm<<<dim3(QKV / BN, TOK / BM), 256>>>(x, w_attn, b_attn);
    score_gemm<<<dim3(SQL / BN, SQL / BM, BSZ * NHH), 256>>>();
    softmax_rows<<<BSZ * NHH * SQL, 128>>>();
    pv_gemm<<<dim3(ED / BN, SQL / BM, BSZ * NHH), 256>>>();
    out_gemm<<<dim3(ED / BN, TOK / BM), 256>>>(w_out, b_out, out);
}